// round 7
// baseline (speedup 1.0000x reference)
#include <cuda_runtime.h>
#include <cstdint>

// Problem constants
#define BB 64      // batch
#define KK 4096    // dim_in
#define OO 4096    // dim_out
#define KW 128     // KK/32 bit-words along k
#define OT 16      // output columns per block (256 blocks)

#define CHUNK_KW   8                    // kw per pipeline chunk
#define CHUNK_ROWS (CHUNK_KW * 32)      // 256 k-rows per chunk
#define NCHUNK     (KW / CHUNK_KW)      // 16 chunks
#define RAW_PITCH  20                   // words per raw row (80B, padded from 64B)
#define RAW_STAGE  (CHUNK_ROWS * RAW_PITCH)  // 5120 words = 20KB per stage

// x bits, transposed for lane-coalesced reads in the main kernel: [kw][b]
__device__ uint32_t g_xbitsT[KW * BB];   // 32 KB

// Robust 0/1 extraction: int32 {0,1} (bit 0) or float32 {0.0f,1.0f} (bit 23).
__device__ __forceinline__ uint32_t bit01(uint32_t w) {
    return (w | (w >> 23)) & 1u;
}

__device__ __forceinline__ void cp_async16(uint32_t saddr, const void* gptr) {
    asm volatile("cp.async.cg.shared.global [%0], [%1], 16;\n"
                 :: "r"(saddr), "l"(gptr));
}
__device__ __forceinline__ void cp_commit() {
    asm volatile("cp.async.commit_group;\n");
}
template <int N>
__device__ __forceinline__ void cp_wait() {
    asm volatile("cp.async.wait_group %0;\n" :: "n"(N));
}

// ---------------------------------------------------------------------------
// Pack x (0/1 words) into bit-words. 8192 threads: one word each.
// ---------------------------------------------------------------------------
__global__ void pack_x_kernel(const uint32_t* __restrict__ x) {
    int t  = blockIdx.x * blockDim.x + threadIdx.x;   // 0..8191
    int kw = t >> 6;
    int b  = t & 63;
    const uint4* p = reinterpret_cast<const uint4*>(x + (size_t)b * KK + kw * 32);
    uint32_t w = 0;
    #pragma unroll
    for (int i = 0; i < 8; i++) {
        uint4 v = p[i];
        w |= bit01(v.x) << (4 * i);
        w |= bit01(v.y) << (4 * i + 1);
        w |= bit01(v.z) << (4 * i + 2);
        w |= bit01(v.w) << (4 * i + 3);
    }
    g_xbitsT[kw * BB + b] = w;
}

// ---------------------------------------------------------------------------
// Main kernel: 256 blocks x 256 threads, 16 output columns per block.
// 16-chunk cp.async pipeline: chunk c+2 streams into raw[(c)&1] while chunk c
// is packed into a bit tile and popcounted.
// ---------------------------------------------------------------------------
__global__ void __launch_bounds__(256, 2) xnor_main_kernel(
    const uint32_t* __restrict__ masks,  // [KK][OO] 0/1 words
    const int*      __restrict__ thr,    // [OO] int32
    float*          __restrict__ out)    // [BB][OO] float32 0/1
{
    __shared__ __align__(16) uint32_t raw[2][RAW_STAGE];        // 40 KB
    __shared__ __align__(16) uint32_t tile[2][CHUNK_KW * OT];   // 1 KB

    const int t  = threadIdx.x;
    const int o0 = blockIdx.x * OT;

    const uint32_t raw_s0 = (uint32_t)__cvta_generic_to_shared(&raw[0][0]);
    const uint32_t raw_s1 = (uint32_t)__cvta_generic_to_shared(&raw[1][0]);

    // ---- cp.async issue for one chunk: 1024 x 16B, 4 per thread ----------
    auto issue_chunk = [&](int c, int stage) {
        const uint32_t sbase = stage ? raw_s1 : raw_s0;
        #pragma unroll
        for (int i = 0; i < 4; i++) {
            int g    = i * 256 + t;
            int rloc = g >> 2;           // local row 0..255
            int quad = g & 3;            // 16B quad within 64B row
            int grow = c * CHUNK_ROWS + rloc;
            const void* gptr = masks + (size_t)grow * OO + o0 + quad * 4;
            cp_async16(sbase + (rloc * RAW_PITCH + quad * 4) * 4, gptr);
        }
        cp_commit();
    };

    // prologue: two chunks in flight
    issue_chunk(0, 0);
    issue_chunk(1, 1);

    // popc thread mapping: lanes = batch, warp -> (half, oset)
    const int lane = t & 31;
    const int warp = t >> 5;
    const int half = warp & 1;
    const int oset = warp >> 1;          // 0..3 -> 4 columns each
    const int b    = half * 32 + lane;

    int acc[4] = {0, 0, 0, 0};

    for (int c = 0; c < NCHUNK; c++) {
        const int stage = c & 1;

        // x bit-words for this chunk (independent of smem; hides under wait)
        uint32_t xr[CHUNK_KW];
        #pragma unroll
        for (int j = 0; j < CHUNK_KW; j++)
            xr[j] = g_xbitsT[(c * CHUNK_KW + j) * BB + b];

        cp_wait<1>();          // chunk c landed (groups 0..c complete)
        __syncthreads();       // raw[stage] visible to all threads

        // ---- pack: raw words -> bit tile [CHUNK_KW][OT] (128 threads) ----
        if (t < CHUNK_KW * OT) {
            const int kwl = t >> 4;      // 0..7
            const int col = t & 15;
            const uint32_t* rp = &raw[stage][kwl * 32 * RAW_PITCH + col];
            uint32_t w = 0;
            #pragma unroll
            for (int j = 0; j < 32; j++)
                w |= bit01(rp[j * RAW_PITCH]) << j;
            tile[stage][kwl * OT + col] = w;
        }
        __syncthreads();       // tile ready; raw[stage] free for reuse

        // refill the stage we just consumed (commit every iter -> stable
        // group numbering for cp_wait<1>)
        if (c + 2 < NCHUNK) issue_chunk(c + 2, stage);
        else                cp_commit();

        // ---- popc: XNOR vs x bits, broadcast tile reads ------------------
        const uint4* t4 = reinterpret_cast<const uint4*>(tile[stage]);
        #pragma unroll
        for (int j = 0; j < CHUNK_KW; j++) {
            const uint32_t xv = xr[j];
            uint4 m = t4[j * 4 + oset];
            acc[0] += __popc(xv ^ m.x);
            acc[1] += __popc(xv ^ m.y);
            acc[2] += __popc(xv ^ m.z);
            acc[3] += __popc(xv ^ m.w);
        }
    }

    // ---- epilogue: threshold + float store --------------------------------
    const int obase = o0 + oset * 4;
    float res[4];
    #pragma unroll
    for (int i = 0; i < 4; i++) {
        int cnt = KK - acc[i];                       // # equal bits (sum XNOR)
        res[i] = (cnt > thr[obase + i]) ? 1.0f : 0.0f;
    }
    *reinterpret_cast<float4*>(out + (size_t)b * OO + obase) =
        make_float4(res[0], res[1], res[2], res[3]);
}

// ---------------------------------------------------------------------------
extern "C" void kernel_launch(void* const* d_in, const int* in_sizes, int n_in,
                              void* d_out, int out_size) {
    // Identify inputs by element count (robust to ordering)
    const void* x     = d_in[0];
    const void* masks = d_in[1];
    const int*  thr   = (const int*)d_in[2];
    for (int i = 0; i < n_in; i++) {
        if      (in_sizes[i] == KK * OO) masks = d_in[i];
        else if (in_sizes[i] == BB * KK) x     = d_in[i];
        else if (in_sizes[i] == OO)      thr   = (const int*)d_in[i];
    }

    pack_x_kernel<<<32, 256>>>((const uint32_t*)x);
    xnor_main_kernel<<<OO / OT, 256>>>((const uint32_t*)masks, thr, (float*)d_out);
}

// round 8
// speedup vs baseline: 1.2935x; 1.2935x over previous
#include <cuda_runtime.h>
#include <cstdint>

// Problem constants
#define BB 64       // batch
#define KK 4096     // dim_in
#define OO 4096     // dim_out
#define KW 128      // KK/32 bit-words along k
#define OT 16       // output columns per strip
#define NSTRIP (OO / OT)   // 256
#define SLABS  4           // k-split
#define SKW    (KW / SLABS) // 32 kw per slab (1024 k-rows)

// x bits, transposed: [kw][b]
__device__ uint32_t g_xbitsT[KW * BB];                 // 32 KB
// partial popc sums: [slab][strip][b][OT]
__device__ uint32_t g_partial[SLABS * NSTRIP * BB * OT];  // 4 MB

// Robust 0/1 extraction: int32 {0,1} (bit 0) or float32 {0.0f,1.0f} (bit 23).
__device__ __forceinline__ uint32_t bit01(uint32_t w) {
    return (w | (w >> 23)) & 1u;
}

// ---------------------------------------------------------------------------
// Pack x (0/1 words) into bit-words. 8192 threads: one word each.
// ---------------------------------------------------------------------------
__global__ void pack_x_kernel(const uint32_t* __restrict__ x) {
    int t  = blockIdx.x * blockDim.x + threadIdx.x;   // 0..8191
    int kw = t >> 6;
    int b  = t & 63;
    const uint4* p = reinterpret_cast<const uint4*>(x + (size_t)b * KK + kw * 32);
    uint32_t w = 0;
    #pragma unroll
    for (int i = 0; i < 8; i++) {
        uint4 v = p[i];
        w |= bit01(v.x) << (4 * i);
        w |= bit01(v.y) << (4 * i + 1);
        w |= bit01(v.z) << (4 * i + 2);
        w |= bit01(v.w) << (4 * i + 3);
    }
    g_xbitsT[kw * BB + b] = w;
}

// ---------------------------------------------------------------------------
// Partial kernel: 1024 blocks (256 strips x 4 k-slabs) x 256 threads.
//   phase 1: pack [1024 k-rows x 16 cols] into a 2KB bit tile (one sync)
//   phase 2: XNOR-popcount vs x bits, write partial sums per (b, o)
// ---------------------------------------------------------------------------
__global__ void __launch_bounds__(256) xnor_partial_kernel(
    const uint32_t* __restrict__ masks)   // [KK][OO] 0/1 words
{
    __shared__ uint32_t tile[SKW * OT];   // 2 KB, layout [kw][o]

    const int t     = threadIdx.x;
    const int strip = blockIdx.x & (NSTRIP - 1);
    const int slab  = blockIdx.x >> 8;
    const int o0    = strip * OT;
    const int kw0   = slab * SKW;

    // ---------------- phase 1: pack mask slab-strip into shared bits -------
    // thread -> (op = column pair 0..7, kwl = 0..31)
    {
        const int op  = t & 7;
        const int kwl = t >> 3;
        const uint2* base = reinterpret_cast<const uint2*>(
            masks + (size_t)((kw0 + kwl) * 32) * OO + o0 + op * 2);
        uint32_t a0 = 0, a1 = 0;
        #pragma unroll 8
        for (int j = 0; j < 32; j++) {
            uint2 m = base[(size_t)j * (OO / 2)];
            a0 |= bit01(m.x) << j;
            a1 |= bit01(m.y) << j;
        }
        *reinterpret_cast<uint2*>(&tile[kwl * OT + op * 2]) = make_uint2(a0, a1);
    }
    __syncthreads();

    // ---------------- phase 2: XNOR popcount over the slab ------------------
    const int lane = t & 31;
    const int warp = t >> 5;
    const int half = warp & 1;        // which 32 batches
    const int oset = warp >> 1;       // 0..3 -> 4 columns each
    const int b    = half * 32 + lane;

    int acc[4] = {0, 0, 0, 0};
    const uint4* t4 = reinterpret_cast<const uint4*>(tile);

    #pragma unroll
    for (int ck = 0; ck < SKW / 8; ck++) {
        uint32_t xr[8];
        #pragma unroll
        for (int j = 0; j < 8; j++)
            xr[j] = g_xbitsT[(kw0 + ck * 8 + j) * BB + b];

        #pragma unroll
        for (int j = 0; j < 8; j++) {
            const uint32_t xv = xr[j];
            uint4 m = t4[(ck * 8 + j) * 4 + oset];   // broadcast
            acc[0] += __popc(xv ^ m.x);
            acc[1] += __popc(xv ^ m.y);
            acc[2] += __popc(xv ^ m.z);
            acc[3] += __popc(xv ^ m.w);
        }
    }

    // partial store: [slab][strip][b][oset*4..+3]
    uint32_t* pp = &g_partial[(((size_t)slab * NSTRIP + strip) * BB + b) * OT + oset * 4];
    *reinterpret_cast<uint4*>(pp) =
        make_uint4((uint32_t)acc[0], (uint32_t)acc[1],
                   (uint32_t)acc[2], (uint32_t)acc[3]);
}

// ---------------------------------------------------------------------------
// Epilogue: sum 4 slab partials, threshold, write float out.
// 256 blocks (one per strip) x 256 threads; each thread does 4 batches.
// ---------------------------------------------------------------------------
__global__ void __launch_bounds__(256) epilogue_kernel(
    const int* __restrict__ thr,    // [OO] int32
    float*     __restrict__ out)    // [BB][OO] float32 0/1
{
    const int t     = threadIdx.x;
    const int strip = blockIdx.x;
    const int o_l   = t & 15;
    const int o     = strip * OT + o_l;
    const int th    = thr[o];

    #pragma unroll
    for (int i = 0; i < 4; i++) {
        const int b = (t >> 4) + i * 16;
        int s = 0;
        #pragma unroll
        for (int sl = 0; sl < SLABS; sl++)
            s += (int)g_partial[(((size_t)sl * NSTRIP + strip) * BB + b) * OT + o_l];
        // # equal bits = KK - hamming
        out[(size_t)b * OO + o] = ((KK - s) > th) ? 1.0f : 0.0f;
    }
}

// ---------------------------------------------------------------------------
extern "C" void kernel_launch(void* const* d_in, const int* in_sizes, int n_in,
                              void* d_out, int out_size) {
    // Identify inputs by element count (robust to ordering)
    const void* x     = d_in[0];
    const void* masks = d_in[1];
    const int*  thr   = (const int*)d_in[2];
    for (int i = 0; i < n_in; i++) {
        if      (in_sizes[i] == KK * OO) masks = d_in[i];
        else if (in_sizes[i] == BB * KK) x     = d_in[i];
        else if (in_sizes[i] == OO)      thr   = (const int*)d_in[i];
    }

    pack_x_kernel<<<32, 256>>>((const uint32_t*)x);
    xnor_partial_kernel<<<NSTRIP * SLABS, 256>>>((const uint32_t*)masks);
    epilogue_kernel<<<NSTRIP, 256>>>(thr, (float*)d_out);
}

// round 10
// speedup vs baseline: 1.3814x; 1.0680x over previous
#include <cuda_runtime.h>
#include <cstdint>

// Problem constants
#define BB 64       // batch
#define KK 4096     // dim_in
#define OO 4096     // dim_out
#define KW 128      // KK/32 bit-words along k
#define OT 16       // output columns per strip
#define NSTRIP (OO / OT)    // 256
#define SLABS  4            // k-split
#define SKW    (KW / SLABS) // 32 kw per slab (1024 k-rows)

// x bits, transposed: [kw][b]
__device__ uint32_t g_xbitsT[KW * BB];                    // 32 KB
// partial popc sums: [slab][strip][b][OT]
__device__ uint32_t g_partial[SLABS * NSTRIP * BB * OT];  // 4 MB

// Robust 0/1 extraction: int32 {0,1} (bit 0) or float32 {0.0f,1.0f} (bit 23).
__device__ __forceinline__ uint32_t bit01(uint32_t w) {
    return (w | (w >> 23)) & 1u;
}

// ---------------------------------------------------------------------------
// Pack x via warp ballot: one thread per element, one LDG.32 + ballot.
// Warp lanes = 32 consecutive k of one batch row, so the ballot word IS the
// packed word (bit j = element kw*32+j). 1024 blocks x 256 threads.
// ---------------------------------------------------------------------------
__global__ void __launch_bounds__(256) pack_x_kernel(const uint32_t* __restrict__ x) {
    const int g = blockIdx.x * 256 + threadIdx.x;   // 0..262143 -> (b, k)
    const uint32_t v = bit01(x[g]);
    const uint32_t w = __ballot_sync(0xFFFFFFFFu, v);
    if ((threadIdx.x & 31) == 0) {
        const int k  = g & (KK - 1);
        const int b  = g >> 12;          // / KK
        g_xbitsT[(k >> 5) * BB + b] = w;
    }
}

// ---------------------------------------------------------------------------
// Partial kernel: 1024 blocks (256 strips x 4 k-slabs) x 256 threads.
//   phase 1: pack [1024 k-rows x 16 cols] into a 2KB bit tile (one sync)
//   phase 2: XNOR-popcount vs x bits, write partial sums per (b, o)
// ---------------------------------------------------------------------------
__global__ void __launch_bounds__(256) xnor_partial_kernel(
    const uint32_t* __restrict__ masks)   // [KK][OO] 0/1 words
{
    __shared__ uint32_t tile[SKW * OT];   // 2 KB, layout [kw][o]

    const int t     = threadIdx.x;
    const int strip = blockIdx.x & (NSTRIP - 1);
    const int slab  = blockIdx.x >> 8;
    const int o0    = strip * OT;
    const int kw0   = slab * SKW;

    // ---------------- phase 1: pack mask slab-strip into shared bits -------
    // thread -> (op = column pair 0..7, kwl = 0..31)
    {
        const int op  = t & 7;
        const int kwl = t >> 3;
        const uint2* base = reinterpret_cast<const uint2*>(
            masks + (size_t)((kw0 + kwl) * 32) * OO + o0 + op * 2);
        uint32_t a0 = 0, a1 = 0;
        #pragma unroll 8
        for (int j = 0; j < 32; j++) {
            uint2 m = base[(size_t)j * (OO / 2)];
            a0 |= bit01(m.x) << j;
            a1 |= bit01(m.y) << j;
        }
        *reinterpret_cast<uint2*>(&tile[kwl * OT + op * 2]) = make_uint2(a0, a1);
    }
    __syncthreads();

    // ---------------- phase 2: XNOR popcount over the slab ------------------
    const int lane = t & 31;
    const int warp = t >> 5;
    const int half = warp & 1;        // which 32 batches
    const int oset = warp >> 1;       // 0..3 -> 4 columns each
    const int b    = half * 32 + lane;

    int acc[4] = {0, 0, 0, 0};
    const uint4* t4 = reinterpret_cast<const uint4*>(tile);

    #pragma unroll
    for (int ck = 0; ck < SKW / 8; ck++) {
        uint32_t xr[8];
        #pragma unroll
        for (int j = 0; j < 8; j++)
            xr[j] = g_xbitsT[(kw0 + ck * 8 + j) * BB + b];

        #pragma unroll
        for (int j = 0; j < 8; j++) {
            const uint32_t xv = xr[j];
            uint4 m = t4[(ck * 8 + j) * 4 + oset];   // broadcast
            acc[0] += __popc(xv ^ m.x);
            acc[1] += __popc(xv ^ m.y);
            acc[2] += __popc(xv ^ m.z);
            acc[3] += __popc(xv ^ m.w);
        }
    }

    // partial store: [slab][strip][b][oset*4..+3]
    uint32_t* pp = &g_partial[(((size_t)slab * NSTRIP + strip) * BB + b) * OT + oset * 4];
    *reinterpret_cast<uint4*>(pp) =
        make_uint4((uint32_t)acc[0], (uint32_t)acc[1],
                   (uint32_t)acc[2], (uint32_t)acc[3]);
}

// ---------------------------------------------------------------------------
// Epilogue: sum 4 slab partials, threshold, write float out.
// 256 blocks (one per strip) x 256 threads; each thread does 4 batches.
// ---------------------------------------------------------------------------
__global__ void __launch_bounds__(256) epilogue_kernel(
    const int* __restrict__ thr,    // [OO] int32
    float*     __restrict__ out)    // [BB][OO] float32 0/1
{
    const int t     = threadIdx.x;
    const int strip = blockIdx.x;
    const int o_l   = t & 15;
    const int o     = strip * OT + o_l;
    const int th    = thr[o];

    #pragma unroll
    for (int i = 0; i < 4; i++) {
        const int b = (t >> 4) + i * 16;
        int s = 0;
        #pragma unroll
        for (int sl = 0; sl < SLABS; sl++)
            s += (int)g_partial[(((size_t)sl * NSTRIP + strip) * BB + b) * OT + o_l];
        // # equal bits = KK - hamming
        out[(size_t)b * OO + o] = ((KK - s) > th) ? 1.0f : 0.0f;
    }
}

// ---------------------------------------------------------------------------
extern "C" void kernel_launch(void* const* d_in, const int* in_sizes, int n_in,
                              void* d_out, int out_size) {
    // Identify inputs by element count (robust to ordering)
    const void* x     = d_in[0];
    const void* masks = d_in[1];
    const int*  thr   = (const int*)d_in[2];
    for (int i = 0; i < n_in; i++) {
        if      (in_sizes[i] == KK * OO) masks = d_in[i];
        else if (in_sizes[i] == BB * KK) x     = d_in[i];
        else if (in_sizes[i] == OO)      thr   = (const int*)d_in[i];
    }

    pack_x_kernel<<<(BB * KK) / 256, 256>>>((const uint32_t*)x);
    xnor_partial_kernel<<<NSTRIP * SLABS, 256>>>((const uint32_t*)masks);
    epilogue_kernel<<<NSTRIP, 256>>>(thr, (float*)d_out);
}